// round 3
// baseline (speedup 1.0000x reference)
#include <cuda_runtime.h>
#include <cstdint>

#define T_SEQ 512
#define H 32
#define WPB 2          // warps per block in recurrence kernel
#define MAXB 4096

typedef unsigned long long u64;

// scratch for precomputed layer-1 input projection: xin[b][t][i]
__device__ float g_xin[(size_t)MAXB * T_SEQ * H];

__device__ __forceinline__ u64 fma2(u64 a, u64 b, u64 c) {
    u64 d;
    asm("fma.rn.f32x2 %0, %1, %2, %3;" : "=l"(d) : "l"(a), "l"(b), "l"(c));
    return d;
}
__device__ __forceinline__ u64 add2(u64 a, u64 b) {
    u64 d;
    asm("add.rn.f32x2 %0, %1, %2;" : "=l"(d) : "l"(a), "l"(b));
    return d;
}
__device__ __forceinline__ float lo_hi_sum(u64 a) {
    unsigned lo, hi;
    asm("mov.b64 {%0,%1}, %2;" : "=r"(lo), "=r"(hi) : "l"(a));
    return __uint_as_float(lo) + __uint_as_float(hi);
}
// tanh(x) = 1 - 2/(exp(2x)+1). exp overflow -> inf -> 2/inf = 0 -> 1. abs err ~1e-7.
__device__ __forceinline__ float tanh_fast(float x) {
    float e = __expf(2.0f * x);
    return 1.0f - __fdividef(2.0f, e + 1.0f);
}

// ============================================================================
// K1: xin[b][t][i] = sum_j x[b][t][j] * W_ih1[i][j] + (b_ih1[i] + b_hh1[i])
// Each warp: 16 rows (4 groups of 4), lane = output i. Coalesced in, coalesced out.
// ============================================================================
__global__ __launch_bounds__(128)
void xin_kernel(const float* __restrict__ x,
                const float* __restrict__ W_ih1,
                const float* __restrict__ b_ih1,
                const float* __restrict__ b_hh1)
{
    const int lane = threadIdx.x & 31;
    const int wid  = threadIdx.x >> 5;
    const long long r0 = ((long long)blockIdx.x * 4 + wid) * 16;

    __shared__ __align__(16) float s[4][2][4 * H];   // [warp][buf][4 rows x 32]

    // per-lane weight row (packed f32x2)
    u64 w[16];
    {
        const u64* p = (const u64*)(W_ih1 + lane * H);
        #pragma unroll
        for (int k = 0; k < 16; k++) w[k] = p[k];
    }
    const float bias = b_ih1[lane] + b_hh1[lane];

    const float* xb = x + r0 * H;
    float* ob = g_xin + r0 * H;

    // prefetch group 0 (4 rows = 512B contiguous; lane takes 16B)
    float4 pre = *(const float4*)(xb + lane * 4);

    #pragma unroll
    for (int g = 0; g < 4; g++) {
        const int buf = g & 1;
        *(float4*)&s[wid][buf][lane * 4] = pre;
        if (g < 3) pre = *(const float4*)(xb + (g + 1) * 4 * H + lane * 4);
        __syncwarp();

        #pragma unroll
        for (int rr = 0; rr < 4; rr++) {
            const ulonglong2* xv = (const ulonglong2*)&s[wid][buf][rr * H];
            u64 a0 = 0ull, a1 = 0ull;
            #pragma unroll
            for (int k = 0; k < 8; k++) {
                ulonglong2 v = xv[k];
                a0 = fma2(v.x, w[2 * k],     a0);
                a1 = fma2(v.y, w[2 * k + 1], a1);
            }
            ob[(g * 4 + rr) * H + lane] = lo_hi_sum(add2(a0, a1)) + bias;
        }
        __syncwarp();   // group's reads done before next overwrite of other buf's neighbor? (double buffer -> protects buf reuse at g+2)
    }
}

// ============================================================================
// K2: fused 2-layer recurrence, one warp per batch element, lane = unit i.
//   h1_t = tanh(xin[t]      + W_hh1 h1_{t-1})
//   h2_t = tanh(W_ih2 h1_t  + W_hh2 h2_{t-1} + b2)
// ============================================================================
__global__ __launch_bounds__(WPB * 32, 7)
void rnn_rec_kernel(const float* __restrict__ W_hh1,
                    const float* __restrict__ W_ih2,
                    const float* __restrict__ W_hh2,
                    const float* __restrict__ b_ih2,
                    const float* __restrict__ b_hh2,
                    const float* __restrict__ W_fc,
                    const float* __restrict__ b_fc,
                    float* __restrict__ out, int Bn)
{
    const int lane = threadIdx.x & 31;
    const int wid  = threadIdx.x >> 5;
    const int b    = blockIdx.x * WPB + wid;
    if (b >= Bn) return;

    // [warp][pingpong by t&1][ h1:0..31 | h2:32..63 ]
    __shared__ __align__(16) float s_hh[WPB][2][2 * H];

    u64 whh1[16], wcat[32];    // wcat[0:16]=W_ih2 row, [16:32]=W_hh2 row
    {
        const u64* p1 = (const u64*)(W_hh1 + lane * H);
        const u64* p2 = (const u64*)(W_ih2 + lane * H);
        const u64* p3 = (const u64*)(W_hh2 + lane * H);
        #pragma unroll
        for (int k = 0; k < 16; k++) {
            whh1[k]     = p1[k];
            wcat[k]     = p2[k];
            wcat[16 + k] = p3[k];
        }
    }
    const float bias2 = b_ih2[lane] + b_hh2[lane];

    const float* xg = g_xin + (size_t)b * T_SEQ * H + lane;

    float h2_reg = 0.0f;
    s_hh[wid][1][lane] = 0.0f;        // h1_{-1}, read by phase A at t=0 (buf p^1 = 1)
    __syncwarp();

    // xin stream: prefetch 4 timesteps ahead (independent LDGs, MLP=4)
    float nxt0 = xg[0 * H], nxt1 = xg[1 * H], nxt2 = xg[2 * H], nxt3 = xg[3 * H];
    float cur0 = 0.f, cur1 = 0.f, cur2 = 0.f, cur3 = 0.f;

    #pragma unroll 4
    for (int t = 0; t < T_SEQ; ++t) {
        const int p = t & 1;

        if ((t & 3) == 0) {
            cur0 = nxt0; cur1 = nxt1; cur2 = nxt2; cur3 = nxt3;
            const int tn = (t + 4 <= T_SEQ - 4) ? (t + 4) : (T_SEQ - 4);
            nxt0 = xg[(size_t)(tn + 0) * H];
            nxt1 = xg[(size_t)(tn + 1) * H];
            nxt2 = xg[(size_t)(tn + 2) * H];
            nxt3 = xg[(size_t)(tn + 3) * H];
        }
        const float cur = ((t & 3) == 0) ? cur0 : ((t & 3) == 1) ? cur1
                        : ((t & 3) == 2) ? cur2 : cur3;

        // publish h2_{t-1} (read only by THIS step's phase B, after the syncwarp)
        s_hh[wid][p][H + lane] = h2_reg;

        // ---- phase A: h1_t (reads previous buffer only -> no sync needed) ----
        const ulonglong2* h1o = (const ulonglong2*)&s_hh[wid][p ^ 1][0];
        u64 a0 = 0ull, a1 = 0ull;
        #pragma unroll
        for (int k = 0; k < 8; k++) {
            ulonglong2 v = h1o[k];
            a0 = fma2(v.x, whh1[2 * k],     a0);
            a1 = fma2(v.y, whh1[2 * k + 1], a1);
        }
        const float h1n = tanh_fast(lo_hi_sum(add2(a0, a1)) + cur);

        s_hh[wid][p][lane] = h1n;     // publish h1_t
        __syncwarp();                 // single barrier covers both publishes

        // ---- phase B: h2_t over concatenated [h1_t ; h2_{t-1}] ----
        const ulonglong2* hv = (const ulonglong2*)&s_hh[wid][p][0];
        u64 c0 = 0ull, c1 = 0ull, c2 = 0ull, c3 = 0ull;
        #pragma unroll
        for (int k = 0; k < 16; k++) {
            ulonglong2 v = hv[k];
            if (k & 1) {
                c2 = fma2(v.x, wcat[2 * k],     c2);
                c3 = fma2(v.y, wcat[2 * k + 1], c3);
            } else {
                c0 = fma2(v.x, wcat[2 * k],     c0);
                c1 = fma2(v.y, wcat[2 * k + 1], c1);
            }
        }
        h2_reg = tanh_fast(lo_hi_sum(add2(add2(c0, c2), add2(c1, c3))) + bias2);
    }

    // ---- FC head: out[b] = h2_T . W_fc + b_fc ----
    float v = h2_reg * W_fc[lane];
    #pragma unroll
    for (int o = 16; o; o >>= 1) v += __shfl_xor_sync(0xFFFFFFFFu, v, o);
    if (lane == 0) out[b] = v + b_fc[0];
}

extern "C" void kernel_launch(void* const* d_in, const int* in_sizes, int n_in,
                              void* d_out, int out_size)
{
    const float* x     = (const float*)d_in[0];
    const float* W_ih1 = (const float*)d_in[1];
    const float* W_hh1 = (const float*)d_in[2];
    const float* b_ih1 = (const float*)d_in[3];
    const float* b_hh1 = (const float*)d_in[4];
    const float* W_ih2 = (const float*)d_in[5];
    const float* W_hh2 = (const float*)d_in[6];
    const float* b_ih2 = (const float*)d_in[7];
    const float* b_hh2 = (const float*)d_in[8];
    const float* W_fc  = (const float*)d_in[9];
    const float* b_fc  = (const float*)d_in[10];
    float* out = (float*)d_out;

    const int Bn = in_sizes[0] / (T_SEQ * H);

    // K1: xin precompute. 64 rows per block (4 warps x 16 rows).
    const int rows = Bn * T_SEQ;
    xin_kernel<<<rows / 64, 128>>>(x, W_ih1, b_ih1, b_hh1);

    // K2: fused recurrence.
    rnn_rec_kernel<<<(Bn + WPB - 1) / WPB, WPB * 32>>>(
        W_hh1, W_ih2, W_hh2, b_ih2, b_hh2, W_fc, b_fc, out, Bn);
}